// round 4
// baseline (speedup 1.0000x reference)
#include <cuda_runtime.h>

#define BB 4096
#define TT 2048
#define HH 10

union F2U { float2 f; unsigned long long u; };

__device__ __forceinline__ float2 ffma2(float2 a, float2 b, float2 c) {
    F2U ua, ub, uc, ud;
    ua.f = a; ub.f = b; uc.f = c;
    asm("fma.rn.f32x2 %0, %1, %2, %3;" : "=l"(ud.u) : "l"(ua.u), "l"(ub.u), "l"(uc.u));
    return ud.f;
}

__device__ __forceinline__ float tanh_fast(float x) {
    float y;
    asm("tanh.approx.f32 %0, %1;" : "=f"(y) : "f"(x));
    return y;
}

// One hidden unit per thread, 3 LSTM batch elements per warp (lanes 0..29).
// Single-warp CTAs (1366) so the HW balances warps/SMSP and shuffle load/SM.
// h/c in registers; h exchanged via shfl. Gates: f32x2 packed FMA chains,
// activations MUFU.TANH (sigmoid 0.5-scale folded into weights/biases).
// Outputs buffered in a float4, one STG.128 per 4 steps.
__global__ void __launch_bounds__(32) lstm_fused_kernel(
    const float* __restrict__ x,      // [B, T, 1]
    const float* __restrict__ W_ih,   // [4H, 1]
    const float* __restrict__ W_hh,   // [4H, H]
    const float* __restrict__ b_ih,   // [4H]
    const float* __restrict__ b_hh,   // [4H]
    const float* __restrict__ W_out,  // [1, H]
    const float* __restrict__ b_out,  // [1]
    float* __restrict__ out)          // [B, T, 1]
{
    const int lane = threadIdx.x & 31;

    int ew = lane / HH;              // element-within-warp: 0..2 (lanes 30,31 idle)
    int j  = lane - ew * HH;         // hidden unit 0..9
    bool active = (ew < 3);
    int base = ew * HH;
    if (!active) { base = 0; j = 0; }

    int b = blockIdx.x * 3 + ew;
    if (b >= BB) active = false;
    const int bb = active ? b : 0;

    // ---- per-thread constants (sigmoid gates pre-scaled by 0.5) ----
    float2 wi2[5], wf2[5], wg2[5], wo2[5], wout2[5];
#pragma unroll
    for (int m = 0; m < 5; m++) {
        wi2[m] = make_float2(0.5f * W_hh[(0 * HH + j) * HH + 2 * m],
                             0.5f * W_hh[(0 * HH + j) * HH + 2 * m + 1]);
        wf2[m] = make_float2(0.5f * W_hh[(1 * HH + j) * HH + 2 * m],
                             0.5f * W_hh[(1 * HH + j) * HH + 2 * m + 1]);
        wg2[m] = make_float2(W_hh[(2 * HH + j) * HH + 2 * m],
                             W_hh[(2 * HH + j) * HH + 2 * m + 1]);
        wo2[m] = make_float2(0.5f * W_hh[(3 * HH + j) * HH + 2 * m],
                             0.5f * W_hh[(3 * HH + j) * HH + 2 * m + 1]);
        wout2[m] = make_float2(W_out[2 * m], W_out[2 * m + 1]);
    }
    // gate-init pairs: (wx, 0) and (b, 0) so init is one ffma2 with x2=(x,x)
    const float2 wxi2 = make_float2(0.5f * W_ih[0 * HH + j], 0.0f);
    const float2 wxf2 = make_float2(0.5f * W_ih[1 * HH + j], 0.0f);
    const float2 wxg2 = make_float2(       W_ih[2 * HH + j], 0.0f);
    const float2 wxo2 = make_float2(0.5f * W_ih[3 * HH + j], 0.0f);
    const float2 bi2 = make_float2(0.5f * (b_ih[0 * HH + j] + b_hh[0 * HH + j]), 0.0f);
    const float2 bf2 = make_float2(0.5f * (b_ih[1 * HH + j] + b_hh[1 * HH + j]), 0.0f);
    const float2 bg2 = make_float2(       (b_ih[2 * HH + j] + b_hh[2 * HH + j]), 0.0f);
    const float2 bo2 = make_float2(0.5f * (b_ih[3 * HH + j] + b_hh[3 * HH + j]), 0.0f);
    const float2 bout2 = make_float2(b_out[0], 0.0f);

    const float* xp = x   + (size_t)bb * TT;
    float*       op = out + (size_t)bb * TT;
    const bool do_out = active && (j == 0);

    float h = 0.0f, c = 0.0f;
    float4 obuf;

    // One LSTM step: gathers h[t-1], returns its output projection, updates h/c.
    auto step = [&](float xv) -> float {
        float2 hh2[5];
#pragma unroll
        for (int m = 0; m < 5; m++) {
            hh2[m].x = __shfl_sync(0xffffffffu, h, base + 2 * m);
            hh2[m].y = __shfl_sync(0xffffffffu, h, base + 2 * m + 1);
        }

        float2 oacc = ffma2(hh2[0], wout2[0], bout2);
#pragma unroll
        for (int m = 1; m < 5; m++) oacc = ffma2(hh2[m], wout2[m], oacc);

        float2 x2 = make_float2(xv, xv);
        float2 aI = ffma2(x2, wxi2, bi2);
        float2 aF = ffma2(x2, wxf2, bf2);
        float2 aG = ffma2(x2, wxg2, bg2);
        float2 aO = ffma2(x2, wxo2, bo2);
#pragma unroll
        for (int m = 0; m < 5; m++) {
            aI = ffma2(hh2[m], wi2[m], aI);
            aF = ffma2(hh2[m], wf2[m], aF);
            aG = ffma2(hh2[m], wg2[m], aG);
            aO = ffma2(hh2[m], wo2[m], aO);
        }
        float si = fmaf(tanh_fast(aI.x + aI.y), 0.5f, 0.5f);
        float sf = fmaf(tanh_fast(aF.x + aF.y), 0.5f, 0.5f);
        float g  =      tanh_fast(aG.x + aG.y);
        float so = fmaf(tanh_fast(aO.x + aO.y), 0.5f, 0.5f);
        c = fmaf(sf, c, si * g);
        h = so * tanh_fast(c);
        return oacc.x + oacc.y;
    };

    // ---- t = 0..3 (block 0): no store yet ----
    float4 x4 = *(const float4*)xp;
    float4 xn4 = *(const float4*)(xp + 4);
    (void)step(x4.x);                 // h[-1]=0 projection discarded
    obuf.x = step(x4.y);              // out[0]
    obuf.y = step(x4.z);              // out[1]
    obuf.z = step(x4.w);              // out[2]
    x4 = xn4;

    // ---- blocks 1..511 ----
    for (int u = 1; u < TT / 4; u++) {
        xn4 = *(const float4*)(xp + ((u + 1 < TT / 4) ? 4 * u + 4 : 4 * u));
        obuf.w = step(x4.x);          // out[4u-1] completes the quad
        if (do_out) *(float4*)(op + 4 * u - 4) = obuf;
        obuf.x = step(x4.y);          // out[4u]
        obuf.y = step(x4.z);          // out[4u+1]
        obuf.z = step(x4.w);          // out[4u+2]
        x4 = xn4;
    }

    // ---- final: out[T-1] from last h ----
    {
        float2 hh2[5];
#pragma unroll
        for (int m = 0; m < 5; m++) {
            hh2[m].x = __shfl_sync(0xffffffffu, h, base + 2 * m);
            hh2[m].y = __shfl_sync(0xffffffffu, h, base + 2 * m + 1);
        }
        float2 oacc = ffma2(hh2[0], wout2[0], bout2);
#pragma unroll
        for (int m = 1; m < 5; m++) oacc = ffma2(hh2[m], wout2[m], oacc);
        obuf.w = oacc.x + oacc.y;
        if (do_out) *(float4*)(op + TT - 4) = obuf;
    }
}

extern "C" void kernel_launch(void* const* d_in, const int* in_sizes, int n_in,
                              void* d_out, int out_size) {
    const float* x     = (const float*)d_in[0];
    const float* W_ih  = (const float*)d_in[1];
    const float* W_hh  = (const float*)d_in[2];
    const float* b_ih  = (const float*)d_in[3];
    const float* b_hh  = (const float*)d_in[4];
    const float* W_out = (const float*)d_in[5];
    const float* b_out = (const float*)d_in[6];
    float* out = (float*)d_out;

    // single-warp CTAs: 3 elements each -> 1366 blocks; HW balances SMSPs
    const int grid = (BB + 2) / 3;  // 1366
    lstm_fused_kernel<<<grid, 32>>>(x, W_ih, W_hh, b_ih, b_hh, W_out, b_out, out);
}

// round 5
// speedup vs baseline: 1.1435x; 1.1435x over previous
#include <cuda_runtime.h>

#define BB 4096
#define TT 2048
#define HH 10

union F2U { float2 f; unsigned long long u; };

__device__ __forceinline__ float2 ffma2(float2 a, float2 b, float2 c) {
    F2U ua, ub, uc, ud;
    ua.f = a; ub.f = b; uc.f = c;
    asm("fma.rn.f32x2 %0, %1, %2, %3;" : "=l"(ud.u) : "l"(ua.u), "l"(ub.u), "l"(uc.u));
    return ud.f;
}

__device__ __forceinline__ float tanh_fast(float x) {
    float y;
    asm("tanh.approx.f32 %0, %1;" : "=f"(y) : "f"(x));
    return y;
}

// One hidden unit per thread, 3 LSTM elements per warp (lanes 0..29), 4 warps
// per CTA (one per SMSP). h exchanged via double-buffered warp-private SMEM
// broadcast (1 STS + 3 LDS per step) instead of 10 SHFLs. Gates: f32x2 FMA
// chains; activations MUFU.TANH with sigmoid 0.5-scale folded into weights.
// Outputs buffered into one STG.128 per 4 steps; x read via float4.
__global__ void __launch_bounds__(128) lstm_fused_kernel(
    const float* __restrict__ x,      // [B, T, 1]
    const float* __restrict__ W_ih,   // [4H, 1]
    const float* __restrict__ W_hh,   // [4H, H]
    const float* __restrict__ b_ih,   // [4H]
    const float* __restrict__ b_hh,   // [4H]
    const float* __restrict__ W_out,  // [1, H]
    const float* __restrict__ b_out,  // [1]
    float* __restrict__ out)          // [B, T, 1]
{
    // [buf][warp][slot][12 floats]  (slot 3 = scratch for idle lanes)
    __shared__ float hx[2][4][4][12];

    const int tid  = threadIdx.x;
    const int lane = tid & 31;
    const int w    = tid >> 5;

    int ew = lane / HH;              // 0..2 element, 3 = idle lanes 30,31
    int j  = lane - ew * HH;         // hidden unit 0..9 (idle: 0,1)
    bool active = (ew < 3);

    int b = (blockIdx.x * 4 + w) * 3 + ew;
    if (b >= BB) active = false;
    const int bb = active ? b : 0;

    // zero the exchange buffers (covers h0 = 0 and scratch slots)
    {
        float* s = &hx[0][0][0][0];
        for (int i = tid; i < 2 * 4 * 4 * 12; i += 128) s[i] = 0.0f;
    }
    __syncthreads();

    // ---- per-thread constants (sigmoid gates pre-scaled by 0.5) ----
    float2 wi2[5], wf2[5], wg2[5], wo2[5], wout2[5];
#pragma unroll
    for (int m = 0; m < 5; m++) {
        wi2[m] = make_float2(0.5f * W_hh[(0 * HH + j) * HH + 2 * m],
                             0.5f * W_hh[(0 * HH + j) * HH + 2 * m + 1]);
        wf2[m] = make_float2(0.5f * W_hh[(1 * HH + j) * HH + 2 * m],
                             0.5f * W_hh[(1 * HH + j) * HH + 2 * m + 1]);
        wg2[m] = make_float2(W_hh[(2 * HH + j) * HH + 2 * m],
                             W_hh[(2 * HH + j) * HH + 2 * m + 1]);
        wo2[m] = make_float2(0.5f * W_hh[(3 * HH + j) * HH + 2 * m],
                             0.5f * W_hh[(3 * HH + j) * HH + 2 * m + 1]);
        wout2[m] = make_float2(W_out[2 * m], W_out[2 * m + 1]);
    }
    const float2 wxi2 = make_float2(0.5f * W_ih[0 * HH + j], 0.0f);
    const float2 wxf2 = make_float2(0.5f * W_ih[1 * HH + j], 0.0f);
    const float2 wxg2 = make_float2(       W_ih[2 * HH + j], 0.0f);
    const float2 wxo2 = make_float2(0.5f * W_ih[3 * HH + j], 0.0f);
    const float2 bi2 = make_float2(0.5f * (b_ih[0 * HH + j] + b_hh[0 * HH + j]), 0.0f);
    const float2 bf2 = make_float2(0.5f * (b_ih[1 * HH + j] + b_hh[1 * HH + j]), 0.0f);
    const float2 bg2 = make_float2(       (b_ih[2 * HH + j] + b_hh[2 * HH + j]), 0.0f);
    const float2 bo2 = make_float2(0.5f * (b_ih[3 * HH + j] + b_hh[3 * HH + j]), 0.0f);
    const float2 bout2 = make_float2(b_out[0], 0.0f);

    const float* xp = x   + (size_t)bb * TT;
    float*       op = out + (size_t)bb * TT;
    const bool do_out = active && (j == 0);

    const float* rd0 = &hx[0][w][ew][0];   // LDS base, buf 0
    const float* rd1 = &hx[1][w][ew][0];   // LDS base, buf 1
    float*       wr0 = &hx[0][w][ew][j];   // STS addr, buf 0
    float*       wr1 = &hx[1][w][ew][j];   // STS addr, buf 1

    float c = 0.0f;
    float4 obuf;

    // One step: reads h[t-1] from rd, writes h[t] to wr, returns out proj of h[t-1].
    auto step = [&](float xv, const float* rd, float* wr) -> float {
        float4 A = *(const float4*)rd;
        float4 Bv = *(const float4*)(rd + 4);
        float2 C = *(const float2*)(rd + 8);
        float2 hh2[5] = { make_float2(A.x, A.y), make_float2(A.z, A.w),
                          make_float2(Bv.x, Bv.y), make_float2(Bv.z, Bv.w), C };

        float2 oacc = ffma2(hh2[0], wout2[0], bout2);
#pragma unroll
        for (int m = 1; m < 5; m++) oacc = ffma2(hh2[m], wout2[m], oacc);

        float2 x2 = make_float2(xv, xv);
        float2 aI = ffma2(x2, wxi2, bi2);
        float2 aF = ffma2(x2, wxf2, bf2);
        float2 aG = ffma2(x2, wxg2, bg2);
        float2 aO = ffma2(x2, wxo2, bo2);
#pragma unroll
        for (int m = 0; m < 5; m++) {
            aI = ffma2(hh2[m], wi2[m], aI);
            aF = ffma2(hh2[m], wf2[m], aF);
            aG = ffma2(hh2[m], wg2[m], aG);
            aO = ffma2(hh2[m], wo2[m], aO);
        }
        float si = fmaf(tanh_fast(aI.x + aI.y), 0.5f, 0.5f);
        float sf = fmaf(tanh_fast(aF.x + aF.y), 0.5f, 0.5f);
        float g  =      tanh_fast(aG.x + aG.y);
        float so = fmaf(tanh_fast(aO.x + aO.y), 0.5f, 0.5f);
        c = fmaf(sf, c, si * g);
        float h = so * tanh_fast(c);
        *wr = h;
        __syncwarp();
        return oacc.x + oacc.y;
    };

    // ---- t = 0..3: buf parity 0,1,0,1; first projection (h=-1) discarded ----
    float4 x4 = *(const float4*)xp;
    float4 xn4 = *(const float4*)(xp + 4);
    (void)step(x4.x, rd0, wr1);
    obuf.x = step(x4.y, rd1, wr0);    // out[0]
    obuf.y = step(x4.z, rd0, wr1);    // out[1]
    obuf.z = step(x4.w, rd1, wr0);    // out[2]
    x4 = xn4;

    // ---- blocks 1..511 ----
    for (int u = 1; u < TT / 4; u++) {
        xn4 = *(const float4*)(xp + ((u + 1 < TT / 4) ? 4 * u + 4 : 4 * u));
        obuf.w = step(x4.x, rd0, wr1);   // out[4u-1]
        if (do_out) *(float4*)(op + 4 * u - 4) = obuf;
        obuf.x = step(x4.y, rd1, wr0);   // out[4u]
        obuf.y = step(x4.z, rd0, wr1);   // out[4u+1]
        obuf.z = step(x4.w, rd1, wr0);   // out[4u+2]
        x4 = xn4;
    }

    // ---- final: out[T-1] from h[T-1] (sits in buf 0) ----
    {
        float4 A = *(const float4*)rd0;
        float4 Bv = *(const float4*)(rd0 + 4);
        float2 C = *(const float2*)(rd0 + 8);
        float2 hh2[5] = { make_float2(A.x, A.y), make_float2(A.z, A.w),
                          make_float2(Bv.x, Bv.y), make_float2(Bv.z, Bv.w), C };
        float2 oacc = ffma2(hh2[0], wout2[0], bout2);
#pragma unroll
        for (int m = 1; m < 5; m++) oacc = ffma2(hh2[m], wout2[m], oacc);
        obuf.w = oacc.x + oacc.y;
        if (do_out) *(float4*)(op + TT - 4) = obuf;
    }
}

extern "C" void kernel_launch(void* const* d_in, const int* in_sizes, int n_in,
                              void* d_out, int out_size) {
    const float* x     = (const float*)d_in[0];
    const float* W_ih  = (const float*)d_in[1];
    const float* W_hh  = (const float*)d_in[2];
    const float* b_ih  = (const float*)d_in[3];
    const float* b_hh  = (const float*)d_in[4];
    const float* W_out = (const float*)d_in[5];
    const float* b_out = (const float*)d_in[6];
    float* out = (float*)d_out;

    const int elems_per_block = 12;  // 3 per warp, 4 warps (one per SMSP)
    const int grid = (BB + elems_per_block - 1) / elems_per_block;  // 342
    lstm_fused_kernel<<<grid, 128>>>(x, W_ih, W_hh, b_ih, b_hh, W_out, b_out, out);
}

// round 6
// speedup vs baseline: 1.1922x; 1.0426x over previous
#include <cuda_runtime.h>

#define BB 4096
#define TT 2048
#define HH 10

union F2U { float2 f; unsigned long long u; };

__device__ __forceinline__ float2 ffma2(float2 a, float2 b, float2 c) {
    F2U ua, ub, uc, ud;
    ua.f = a; ub.f = b; uc.f = c;
    asm("fma.rn.f32x2 %0, %1, %2, %3;" : "=l"(ud.u) : "l"(ua.u), "l"(ub.u), "l"(uc.u));
    return ud.f;
}

__device__ __forceinline__ float tanh_fast(float x) {
    float y;
    asm("tanh.approx.f32 %0, %1;" : "=f"(y) : "f"(x));
    return y;
}

// One hidden unit per thread, 3 LSTM elements per warp (lanes 0..29).
// 10-warp CTAs, grid=137 -> at most ONE CTA per SM: uniform 10 warps/SM
// (per-SMSP 3/3/2/2 - the provable minimum imbalance for 1366 warps).
// h exchanged via double-buffered warp-private SMEM broadcast. Gates: f32x2
// FMA chains; activations MUFU.TANH (sigmoid 0.5-scale folded into weights).
// Outputs buffered into one STG.128 per 4 steps; x read via float4.
__global__ void __launch_bounds__(320, 1) lstm_fused_kernel(
    const float* __restrict__ x,      // [B, T, 1]
    const float* __restrict__ W_ih,   // [4H, 1]
    const float* __restrict__ W_hh,   // [4H, H]
    const float* __restrict__ b_ih,   // [4H]
    const float* __restrict__ b_hh,   // [4H]
    const float* __restrict__ W_out,  // [1, H]
    const float* __restrict__ b_out,  // [1]
    float* __restrict__ out)          // [B, T, 1]
{
    // [buf][warp][slot][12 floats]  (slot 3 = scratch for idle lanes)
    __shared__ float hx[2][10][4][12];

    const int tid  = threadIdx.x;
    const int lane = tid & 31;
    const int w    = tid >> 5;

    int ew = lane / HH;              // 0..2 element, 3 = idle lanes 30,31
    int j  = lane - ew * HH;         // hidden unit 0..9 (idle: 0,1)
    bool active = (ew < 3);

    int b = (blockIdx.x * 10 + w) * 3 + ew;
    if (b >= BB) active = false;
    const int bb = active ? b : 0;

    // zero the exchange buffers (covers h0 = 0 and scratch slots)
    {
        float* s = &hx[0][0][0][0];
        for (int i = tid; i < 2 * 10 * 4 * 12; i += 320) s[i] = 0.0f;
    }
    __syncthreads();

    // ---- per-thread constants (sigmoid gates pre-scaled by 0.5) ----
    float2 wi2[5], wf2[5], wg2[5], wo2[5], wout2[5];
#pragma unroll
    for (int m = 0; m < 5; m++) {
        wi2[m] = make_float2(0.5f * W_hh[(0 * HH + j) * HH + 2 * m],
                             0.5f * W_hh[(0 * HH + j) * HH + 2 * m + 1]);
        wf2[m] = make_float2(0.5f * W_hh[(1 * HH + j) * HH + 2 * m],
                             0.5f * W_hh[(1 * HH + j) * HH + 2 * m + 1]);
        wg2[m] = make_float2(W_hh[(2 * HH + j) * HH + 2 * m],
                             W_hh[(2 * HH + j) * HH + 2 * m + 1]);
        wo2[m] = make_float2(0.5f * W_hh[(3 * HH + j) * HH + 2 * m],
                             0.5f * W_hh[(3 * HH + j) * HH + 2 * m + 1]);
        wout2[m] = make_float2(W_out[2 * m], W_out[2 * m + 1]);
    }
    const float2 wxi2 = make_float2(0.5f * W_ih[0 * HH + j], 0.0f);
    const float2 wxf2 = make_float2(0.5f * W_ih[1 * HH + j], 0.0f);
    const float2 wxg2 = make_float2(       W_ih[2 * HH + j], 0.0f);
    const float2 wxo2 = make_float2(0.5f * W_ih[3 * HH + j], 0.0f);
    const float2 bi2 = make_float2(0.5f * (b_ih[0 * HH + j] + b_hh[0 * HH + j]), 0.0f);
    const float2 bf2 = make_float2(0.5f * (b_ih[1 * HH + j] + b_hh[1 * HH + j]), 0.0f);
    const float2 bg2 = make_float2(       (b_ih[2 * HH + j] + b_hh[2 * HH + j]), 0.0f);
    const float2 bo2 = make_float2(0.5f * (b_ih[3 * HH + j] + b_hh[3 * HH + j]), 0.0f);
    const float2 bout2 = make_float2(b_out[0], 0.0f);

    const float* xp = x   + (size_t)bb * TT;
    float*       op = out + (size_t)bb * TT;
    const bool do_out = active && (j == 0);

    const float* rd0 = &hx[0][w][ew][0];   // LDS base, buf 0
    const float* rd1 = &hx[1][w][ew][0];   // LDS base, buf 1
    float*       wr0 = &hx[0][w][ew][j];   // STS addr, buf 0
    float*       wr1 = &hx[1][w][ew][j];   // STS addr, buf 1

    float c = 0.0f;
    float4 obuf;

    // One step: reads h[t-1] from rd, writes h[t] to wr, returns out proj of h[t-1].
    auto step = [&](float xv, const float* rd, float* wr) -> float {
        float4 A = *(const float4*)rd;
        float4 Bv = *(const float4*)(rd + 4);
        float2 C = *(const float2*)(rd + 8);
        float2 hh2[5] = { make_float2(A.x, A.y), make_float2(A.z, A.w),
                          make_float2(Bv.x, Bv.y), make_float2(Bv.z, Bv.w), C };

        float2 oacc = ffma2(hh2[0], wout2[0], bout2);
#pragma unroll
        for (int m = 1; m < 5; m++) oacc = ffma2(hh2[m], wout2[m], oacc);

        float2 x2 = make_float2(xv, xv);
        float2 aI = ffma2(x2, wxi2, bi2);
        float2 aF = ffma2(x2, wxf2, bf2);
        float2 aG = ffma2(x2, wxg2, bg2);
        float2 aO = ffma2(x2, wxo2, bo2);
#pragma unroll
        for (int m = 0; m < 5; m++) {
            aI = ffma2(hh2[m], wi2[m], aI);
            aF = ffma2(hh2[m], wf2[m], aF);
            aG = ffma2(hh2[m], wg2[m], aG);
            aO = ffma2(hh2[m], wo2[m], aO);
        }
        float si = fmaf(tanh_fast(aI.x + aI.y), 0.5f, 0.5f);
        float sf = fmaf(tanh_fast(aF.x + aF.y), 0.5f, 0.5f);
        float g  =      tanh_fast(aG.x + aG.y);
        float so = fmaf(tanh_fast(aO.x + aO.y), 0.5f, 0.5f);
        c = fmaf(sf, c, si * g);
        float h = so * tanh_fast(c);
        *wr = h;
        __syncwarp();
        return oacc.x + oacc.y;
    };

    // ---- t = 0..3: buf parity 0,1,0,1; first projection (h=-1) discarded ----
    float4 x4 = *(const float4*)xp;
    float4 xn4 = *(const float4*)(xp + 4);
    (void)step(x4.x, rd0, wr1);
    obuf.x = step(x4.y, rd1, wr0);    // out[0]
    obuf.y = step(x4.z, rd0, wr1);    // out[1]
    obuf.z = step(x4.w, rd1, wr0);    // out[2]
    x4 = xn4;

    // ---- blocks 1..511 ----
    for (int u = 1; u < TT / 4; u++) {
        xn4 = *(const float4*)(xp + ((u + 1 < TT / 4) ? 4 * u + 4 : 4 * u));
        obuf.w = step(x4.x, rd0, wr1);   // out[4u-1]
        if (do_out) *(float4*)(op + 4 * u - 4) = obuf;
        obuf.x = step(x4.y, rd1, wr0);   // out[4u]
        obuf.y = step(x4.z, rd0, wr1);   // out[4u+1]
        obuf.z = step(x4.w, rd1, wr0);   // out[4u+2]
        x4 = xn4;
    }

    // ---- final: out[T-1] from h[T-1] (sits in buf 0) ----
    {
        float4 A = *(const float4*)rd0;
        float4 Bv = *(const float4*)(rd0 + 4);
        float2 C = *(const float2*)(rd0 + 8);
        float2 hh2[5] = { make_float2(A.x, A.y), make_float2(A.z, A.w),
                          make_float2(Bv.x, Bv.y), make_float2(Bv.z, Bv.w), C };
        float2 oacc = ffma2(hh2[0], wout2[0], bout2);
#pragma unroll
        for (int m = 1; m < 5; m++) oacc = ffma2(hh2[m], wout2[m], oacc);
        obuf.w = oacc.x + oacc.y;
        if (do_out) *(float4*)(op + TT - 4) = obuf;
    }
}

extern "C" void kernel_launch(void* const* d_in, const int* in_sizes, int n_in,
                              void* d_out, int out_size) {
    const float* x     = (const float*)d_in[0];
    const float* W_ih  = (const float*)d_in[1];
    const float* W_hh  = (const float*)d_in[2];
    const float* b_ih  = (const float*)d_in[3];
    const float* b_hh  = (const float*)d_in[4];
    const float* W_out = (const float*)d_in[5];
    const float* b_out = (const float*)d_in[6];
    float* out = (float*)d_out;

    // 10-warp CTAs, 30 elements each: 137 CTAs -> <=1 CTA/SM, uniform 10 warps/SM
    const int elems_per_block = 30;
    const int grid = (BB + elems_per_block - 1) / elems_per_block;  // 137
    lstm_fused_kernel<<<grid, 320>>>(x, W_ih, W_hh, b_ih, b_hh, W_out, b_out, out);
}

// round 7
// speedup vs baseline: 1.1932x; 1.0008x over previous
#include <cuda_runtime.h>

#define BB 4096
#define TT 2048
#define HH 10

union F2U { float2 f; unsigned long long u; };

__device__ __forceinline__ float2 ffma2(float2 a, float2 b, float2 c) {
    F2U ua, ub, uc, ud;
    ua.f = a; ub.f = b; uc.f = c;
    asm("fma.rn.f32x2 %0, %1, %2, %3;" : "=l"(ud.u) : "l"(ua.u), "l"(ub.u), "l"(uc.u));
    return ud.f;
}

__device__ __forceinline__ float tanh_fast(float x) {
    float y;
    asm("tanh.approx.f32 %0, %1;" : "=f"(y) : "f"(x));
    return y;
}

// One hidden unit per thread, 3 LSTM elements per warp (lanes 0..29).
// 10-warp CTAs, grid=137 -> <=1 CTA/SM: uniform 10 warps/SM.
// h exchanged via double-buffered warp-private SMEM broadcast with NO
// __syncwarp: the warp is fully converged and the per-warp SMEM pipeline is
// in-order, so the LDS issued after the STS observes the committed values.
// Gates: f32x2 packed FMA chains; activations MUFU.TANH (sigmoid 0.5-scale
// folded into weights/biases). One STG.128 per 4 steps; x via float4.
__global__ void __launch_bounds__(320, 1) lstm_fused_kernel(
    const float* __restrict__ x,      // [B, T, 1]
    const float* __restrict__ W_ih,   // [4H, 1]
    const float* __restrict__ W_hh,   // [4H, H]
    const float* __restrict__ b_ih,   // [4H]
    const float* __restrict__ b_hh,   // [4H]
    const float* __restrict__ W_out,  // [1, H]
    const float* __restrict__ b_out,  // [1]
    float* __restrict__ out)          // [B, T, 1]
{
    // [buf][warp][slot][12 floats]  (slot 3 = scratch for idle lanes)
    __shared__ float hx[2][10][4][12];

    const int tid  = threadIdx.x;
    const int lane = tid & 31;
    const int w    = tid >> 5;

    int ew = lane / HH;              // 0..2 element, 3 = idle lanes 30,31
    int j  = lane - ew * HH;         // hidden unit 0..9 (idle: 0,1)
    bool active = (ew < 3);

    int b = (blockIdx.x * 10 + w) * 3 + ew;
    if (b >= BB) active = false;
    const int bb = active ? b : 0;

    // zero this warp's exchange buffers (h0 = 0 and scratch slots)
    {
        float* s = &hx[0][w][0][0];
        float* s1 = &hx[1][w][0][0];
        for (int i = lane; i < 4 * 12; i += 32) { s[i] = 0.0f; s1[i] = 0.0f; }
    }
    // no cross-warp dependency: each warp only touches hx[*][w][*][*]

    // ---- per-thread constants (sigmoid gates pre-scaled by 0.5) ----
    float2 wi2[5], wf2[5], wg2[5], wo2[5], wout2[5];
#pragma unroll
    for (int m = 0; m < 5; m++) {
        wi2[m] = make_float2(0.5f * W_hh[(0 * HH + j) * HH + 2 * m],
                             0.5f * W_hh[(0 * HH + j) * HH + 2 * m + 1]);
        wf2[m] = make_float2(0.5f * W_hh[(1 * HH + j) * HH + 2 * m],
                             0.5f * W_hh[(1 * HH + j) * HH + 2 * m + 1]);
        wg2[m] = make_float2(W_hh[(2 * HH + j) * HH + 2 * m],
                             W_hh[(2 * HH + j) * HH + 2 * m + 1]);
        wo2[m] = make_float2(0.5f * W_hh[(3 * HH + j) * HH + 2 * m],
                             0.5f * W_hh[(3 * HH + j) * HH + 2 * m + 1]);
        wout2[m] = make_float2(W_out[2 * m], W_out[2 * m + 1]);
    }
    const float2 wxi2 = make_float2(0.5f * W_ih[0 * HH + j], 0.0f);
    const float2 wxf2 = make_float2(0.5f * W_ih[1 * HH + j], 0.0f);
    const float2 wxg2 = make_float2(       W_ih[2 * HH + j], 0.0f);
    const float2 wxo2 = make_float2(0.5f * W_ih[3 * HH + j], 0.0f);
    const float2 bi2 = make_float2(0.5f * (b_ih[0 * HH + j] + b_hh[0 * HH + j]), 0.0f);
    const float2 bf2 = make_float2(0.5f * (b_ih[1 * HH + j] + b_hh[1 * HH + j]), 0.0f);
    const float2 bg2 = make_float2(       (b_ih[2 * HH + j] + b_hh[2 * HH + j]), 0.0f);
    const float2 bo2 = make_float2(0.5f * (b_ih[3 * HH + j] + b_hh[3 * HH + j]), 0.0f);
    const float2 bout2 = make_float2(b_out[0], 0.0f);

    const float* xp = x   + (size_t)bb * TT;
    float*       op = out + (size_t)bb * TT;
    const bool do_out = active && (j == 0);

    const float* rd0 = &hx[0][w][ew][0];   // LDS base, buf 0
    const float* rd1 = &hx[1][w][ew][0];   // LDS base, buf 1
    float*       wr0 = &hx[0][w][ew][j];   // STS addr, buf 0
    float*       wr1 = &hx[1][w][ew][j];   // STS addr, buf 1

    float c = 0.0f;
    float4 obuf;

    // One step: reads h[t-1] from rd, writes h[t] to wr, returns out proj of h[t-1].
    auto step = [&](float xv, const float* rd, float* wr) -> float {
        float4 A = *(const float4*)rd;
        float4 Bv = *(const float4*)(rd + 4);
        float2 C = *(const float2*)(rd + 8);
        float2 hh2[5] = { make_float2(A.x, A.y), make_float2(A.z, A.w),
                          make_float2(Bv.x, Bv.y), make_float2(Bv.z, Bv.w), C };

        float2 oacc = ffma2(hh2[0], wout2[0], bout2);
#pragma unroll
        for (int m = 1; m < 5; m++) oacc = ffma2(hh2[m], wout2[m], oacc);

        float2 x2 = make_float2(xv, xv);
        float2 aI = ffma2(x2, wxi2, bi2);
        float2 aF = ffma2(x2, wxf2, bf2);
        float2 aG = ffma2(x2, wxg2, bg2);
        float2 aO = ffma2(x2, wxo2, bo2);
#pragma unroll
        for (int m = 0; m < 5; m++) {
            aI = ffma2(hh2[m], wi2[m], aI);
            aF = ffma2(hh2[m], wf2[m], aF);
            aG = ffma2(hh2[m], wg2[m], aG);
            aO = ffma2(hh2[m], wo2[m], aO);
        }
        float si = fmaf(tanh_fast(aI.x + aI.y), 0.5f, 0.5f);
        float sf = fmaf(tanh_fast(aF.x + aF.y), 0.5f, 0.5f);
        float g  =      tanh_fast(aG.x + aG.y);
        float so = fmaf(tanh_fast(aO.x + aO.y), 0.5f, 0.5f);
        c = fmaf(sf, c, si * g);
        float h = so * tanh_fast(c);
        *wr = h;   // in-order per-warp SMEM pipe: next step's LDS sees this
        return oacc.x + oacc.y;
    };

    // ---- t = 0..3: buf parity 0,1,0,1; first projection (h=-1) discarded ----
    float4 x4 = *(const float4*)xp;
    float4 xn4 = *(const float4*)(xp + 4);
    (void)step(x4.x, rd0, wr1);
    obuf.x = step(x4.y, rd1, wr0);    // out[0]
    obuf.y = step(x4.z, rd0, wr1);    // out[1]
    obuf.z = step(x4.w, rd1, wr0);    // out[2]
    x4 = xn4;

    // ---- blocks 1..511 ----
    for (int u = 1; u < TT / 4; u++) {
        int un = (u + 1 < TT / 4) ? (u + 1) : u;   // IMNMX-style clamp
        xn4 = *(const float4*)(xp + 4 * un);
        obuf.w = step(x4.x, rd0, wr1);   // out[4u-1]
        if (do_out) *(float4*)(op + 4 * u - 4) = obuf;
        obuf.x = step(x4.y, rd1, wr0);   // out[4u]
        obuf.y = step(x4.z, rd0, wr1);   // out[4u+1]
        obuf.z = step(x4.w, rd1, wr0);   // out[4u+2]
        x4 = xn4;
    }

    // ---- final: out[T-1] from h[T-1] (sits in buf 0) ----
    {
        float4 A = *(const float4*)rd0;
        float4 Bv = *(const float4*)(rd0 + 4);
        float2 C = *(const float2*)(rd0 + 8);
        float2 hh2[5] = { make_float2(A.x, A.y), make_float2(A.z, A.w),
                          make_float2(Bv.x, Bv.y), make_float2(Bv.z, Bv.w), C };
        float2 oacc = ffma2(hh2[0], wout2[0], bout2);
#pragma unroll
        for (int m = 1; m < 5; m++) oacc = ffma2(hh2[m], wout2[m], oacc);
        obuf.w = oacc.x + oacc.y;
        if (do_out) *(float4*)(op + TT - 4) = obuf;
    }
}

extern "C" void kernel_launch(void* const* d_in, const int* in_sizes, int n_in,
                              void* d_out, int out_size) {
    const float* x     = (const float*)d_in[0];
    const float* W_ih  = (const float*)d_in[1];
    const float* W_hh  = (const float*)d_in[2];
    const float* b_ih  = (const float*)d_in[3];
    const float* b_hh  = (const float*)d_in[4];
    const float* W_out = (const float*)d_in[5];
    const float* b_out = (const float*)d_in[6];
    float* out = (float*)d_out;

    // 10-warp CTAs, 30 elements each: 137 CTAs -> <=1 CTA/SM, uniform 10 warps/SM
    const int elems_per_block = 30;
    const int grid = (BB + elems_per_block - 1) / elems_per_block;  // 137
    lstm_fused_kernel<<<grid, 320>>>(x, W_ih, W_hh, b_ih, b_hh, W_out, b_out, out);
}